// round 16
// baseline (speedup 1.0000x reference)
#include <cuda_runtime.h>
#include <cuda_bf16.h>
#include <stdint.h>
#include <math.h>

#define BB 4
#define TT 1024
#define CC 1024
#define HH 16
#define HD 64
#define NEL (BB*TT*CC)          // 4194304
#define NW  (CC*CC)             // 1048576

// ---------------- scratch (device globals: allocation-free) ----------------
__device__ unsigned g_afh[3][NEL/2], g_afl[3][NEL/2];    // q/k/v inputs, A-frag tiles hi/lo
__device__ unsigned g_bfh[4][NW/2],  g_bfl[4][NW/2];     // Wq/Wk/Wv/Wo, B-frag tiles hi/lo
__device__ unsigned g_qfh[NEL/2], g_qfl[NEL/2];          // proj q (x8) flash A-frags
__device__ unsigned g_kfh[NEL/2], g_kfl[NEL/2];          // proj k flash B-frags
__device__ unsigned g_vtf[NEL];                          // proj v tf32 flash B-frags
__device__ unsigned g_qrf[NEL];                          // raw q x8 tf32 flash A-frags
__device__ unsigned g_rtf[32*4096];                      // relpad tf32 B-frag tiles
__device__ unsigned g_ctxfh[NEL/2], g_ctxfl[NEL/2];      // attention out, A-frag tiles hi/lo

// ---------------- helpers ----------------
__device__ __forceinline__ unsigned f2tf32(float x) {
    unsigned u;
    asm("cvt.rna.tf32.f32 %0, %1;" : "=r"(u) : "f"(x));
    return u;
}
__device__ __forceinline__ void mma_tf32(float4& c, const uint4& a, const uint2& b) {
    asm volatile(
        "mma.sync.aligned.m16n8k8.row.col.f32.tf32.tf32.f32 "
        "{%0,%1,%2,%3}, {%4,%5,%6,%7}, {%8,%9}, {%0,%1,%2,%3};"
        : "+f"(c.x), "+f"(c.y), "+f"(c.z), "+f"(c.w)
        : "r"(a.x), "r"(a.y), "r"(a.z), "r"(a.w), "r"(b.x), "r"(b.y));
}
__device__ __forceinline__ void mma_bf16(float4& c, const uint4& a, const uint2& b) {
    asm volatile(
        "mma.sync.aligned.m16n8k16.row.col.f32.bf16.bf16.f32 "
        "{%0,%1,%2,%3}, {%4,%5,%6,%7}, {%8,%9}, {%0,%1,%2,%3};"
        : "+f"(c.x), "+f"(c.y), "+f"(c.z), "+f"(c.w)
        : "r"(a.x), "r"(a.y), "r"(a.z), "r"(a.w), "r"(b.x), "r"(b.y));
}
__device__ __forceinline__ void split_pair(float x, float y, unsigned& hi, unsigned& lo) {
    __nv_bfloat16 hx = __float2bfloat16(x), hy = __float2bfloat16(y);
    __nv_bfloat162 H; H.x = hx; H.y = hy;
    __nv_bfloat162 L;
    L.x = __float2bfloat16(x - __bfloat162float(hx));
    L.y = __float2bfloat16(y - __bfloat162float(hy));
    hi = *reinterpret_cast<unsigned*>(&H);
    lo = *reinterpret_cast<unsigned*>(&L);
}

#define CP16(d, p) asm volatile("cp.async.cg.shared.global [%0], [%1], 16;" :: "r"(d), "l"(p) : "memory")
#define CP_COMMIT() asm volatile("cp.async.commit_group;" ::: "memory")
#define CP_WAIT1()  asm volatile("cp.async.wait_group 1;" ::: "memory")

// A-frag word address for element pair (m, k even): within matrix [M,1024]
__device__ __forceinline__ size_t afrag_addr(int m, int k) {
    int mblk = m >> 7, mr = m & 127, kb = k >> 4, kk = k & 15;
    return (((size_t)mblk * 64 + kb) << 10) + (mr >> 4) * 128
         + ((mr & 7) * 4 + ((kk >> 1) & 3)) * 4 + ((mr >> 3) & 1) + 2 * (kk >> 3);
}
// B-frag word address for element pair (n, k even)
__device__ __forceinline__ size_t bfrag_addr(int n, int k) {
    int nblk = n >> 7, sr = n & 127, kb = k >> 4, kk = k & 15;
    return (((size_t)nblk * 64 + kb) << 10) + (sr >> 3) * 64
         + ((sr & 7) * 4 + ((kk >> 1) & 3)) * 2 + (kk >> 3);
}

// ---------------- fused one-time converts ----------------
__global__ void convAll(const float* __restrict__ q, const float* __restrict__ k,
                        const float* __restrict__ v,
                        const float* __restrict__ Wq, const float* __restrict__ Wk,
                        const float* __restrict__ Wv, const float* __restrict__ Wo,
                        const float* __restrict__ rel_emb,
                        unsigned* __restrict__ afh, unsigned* __restrict__ afl,
                        unsigned* __restrict__ qrf,
                        unsigned* __restrict__ bfh, unsigned* __restrict__ bfl,
                        unsigned* __restrict__ rtf)
{
    int blk = blockIdx.x;
    if (blk < 12288) {
        int arr = blk >> 12;
        int i = ((blk & 4095) << 8) + threadIdx.x;
        const float* src = arr == 0 ? q : (arr == 1 ? k : v);
        float4 v4 = ((const float4*)src)[i];
        unsigned h0, l0, h1, l1;
        split_pair(v4.x, v4.y, h0, l0);
        split_pair(v4.z, v4.w, h1, l1);
        int e = i * 4;
        int m = e >> 10, k0 = e & 1023;
        size_t base = (size_t)arr * (NEL/2) + afrag_addr(m, k0);
        afh[base] = h0; afh[base + 4] = h1;
        afl[base] = l0; afl[base + 4] = l1;
        if (arr == 0) {
            int hh_ = k0 >> 6, d = k0 & 63;
            int b_ = m >> 10, tt = (m >> 7) & 7, mr = m & 127;
            size_t blko = ((size_t)((b_ * 8 + tt) * 16 + hh_)) << 13;
            int qb = ((d >> 3) * 8 + (mr >> 4)) * 128 + (mr & 7) * 16
                   + ((mr >> 3) & 1) + 2 * ((d >> 2) & 1);
            qrf[blko + qb +  0] = f2tf32(8.f * v4.x);
            qrf[blko + qb +  4] = f2tf32(8.f * v4.y);
            qrf[blko + qb +  8] = f2tf32(8.f * v4.z);
            qrf[blko + qb + 12] = f2tf32(8.f * v4.w);
        }
    } else if (blk < 16384) {
        int wblk = blk - 12288;
        int arr = wblk >> 10;
        int i = ((wblk & 1023) << 8) + threadIdx.x;
        const float* src = arr == 0 ? Wq : (arr == 1 ? Wk : (arr == 2 ? Wv : Wo));
        float4 v4 = ((const float4*)src)[i];
        unsigned h0, l0, h1, l1;
        split_pair(v4.x, v4.y, h0, l0);
        split_pair(v4.z, v4.w, h1, l1);
        int e = i * 4;
        int n = e >> 10, k0 = e & 1023;
        size_t base = (size_t)arr * (NW/2) + bfrag_addr(n, k0);
        bfh[base] = h0; bfh[base + 2] = h1;
        bfl[base] = l0; bfl[base + 2] = l1;
    } else {
        int e = ((blk - 16384) << 8) + threadIdx.x;
        int tt = e >> 12, rem = e & 4095;
        int ul = rem >> 6, d = rem & 63;
        int u = tt * 64 + ul;
        int src = u - 24;
        src = src < 0 ? 0 : (src > 1998 ? 1998 : src);
        int addr = tt * 4096 + ((d >> 3) * 8 + (ul >> 3)) * 64
                 + ((ul & 7) * 4 + (d & 3)) * 2 + ((d >> 2) & 1);
        rtf[addr] = f2tf32(rel_emb[src * HD + d]);
    }
}

// ---------------- cp.async 3-stage WIDE GEMM core (128x256 block, K=1024) ----
// Stage layout (words): [Ah 1024 | Al 1024 | Bh 2048 | Bl 2048] = 6144 words = 24 KB.
// 8 warps: wrow = warp&1 (m 64), wcol = warp>>1 (n 64); warp tile 64x64 = 4mt x 8nt.
__device__ __forceinline__ void gemm_core_w(const unsigned* __restrict__ Ahp,
                                            const unsigned* __restrict__ Alp,
                                            const unsigned* __restrict__ Bhp,   // nblk0
                                            const unsigned* __restrict__ Blp,   // nblk0
                                            unsigned* sm, float4 (&acc)[4][8])
{
    const int tid = threadIdx.x;
    const int lane = tid & 31;
    const int warp = tid >> 5;
    const int wrow = warp & 1, wcol = warp >> 1;
    const unsigned sbase = (unsigned)__cvta_generic_to_shared(sm);
    // consumer B base: nblk = wcol>>1 (65536-word blocks in gmem; in smem: nblk*1024)
    const int bntloc = (wcol & 1) * 8;   // local nt base within 128-col block
    const int bsm = 2048 + (wcol >> 1) * 1024;

#define GISSUEW(kb_, s_) { \
        unsigned dd = sbase + (s_) * 24576 + (tid << 4); \
        int off = ((kb_) << 10) + (tid << 2); \
        CP16(dd,          Ahp + off); \
        CP16(dd + 4096,   Alp + off); \
        CP16(dd + 8192,   Bhp + off); \
        CP16(dd + 12288,  Bhp + 65536 + off); \
        CP16(dd + 16384,  Blp + off); \
        CP16(dd + 20480,  Blp + 65536 + off); \
    }

    GISSUEW(0, 0); CP_COMMIT();
    GISSUEW(1, 1); CP_COMMIT();

    int st3 = 0, st3n = 2;
    for (int kb = 0; kb < 64; kb++) {
        CP_WAIT1();
        __syncthreads();
        if (kb < 62) GISSUEW(kb + 2, st3n);
        CP_COMMIT();

        const unsigned* st = sm + st3 * 6144;
        uint4 ah[4], al[4];
#pragma unroll
        for (int i = 0; i < 4; i++) {
            ah[i] = *(const uint4*)&st[(wrow * 4 + i) * 128 + lane * 4];
            al[i] = *(const uint4*)&st[1024 + (wrow * 4 + i) * 128 + lane * 4];
        }
#pragma unroll
        for (int j = 0; j < 8; j++) {
            uint2 bh = *(const uint2*)&st[bsm + (bntloc + j) * 64 + lane * 2];
            uint2 bl = *(const uint2*)&st[bsm + 2048 + (bntloc + j) * 64 + lane * 2];
#pragma unroll
            for (int i = 0; i < 4; i++) {
                mma_bf16(acc[i][j], ah[i], bl);
                mma_bf16(acc[i][j], al[i], bh);
                mma_bf16(acc[i][j], ah[i], bh);
            }
        }
        st3 = st3 == 2 ? 0 : st3 + 1;
        st3n = st3n == 2 ? 0 : st3n + 1;
    }
#undef GISSUEW
}

#define GEMM_SMEM_W 73728

// ========== fused Q/K/V projection GEMM, 128x256 block (blockIdx.z = matrix) ==========
__global__ __launch_bounds__(256, 1)
void gemm_qkv(const unsigned* __restrict__ afh, const unsigned* __restrict__ afl,
              const unsigned* __restrict__ bfh, const unsigned* __restrict__ bfl,
              const float* __restrict__ bq, const float* __restrict__ bk,
              const float* __restrict__ bv,
              unsigned* __restrict__ qfh, unsigned* __restrict__ qfl,
              unsigned* __restrict__ kfh, unsigned* __restrict__ kfl,
              unsigned* __restrict__ vtf)
{
    extern __shared__ unsigned smg[];
    const int z = blockIdx.z;
    const int bm = blockIdx.y * 128, bn = blockIdx.x * 256;
    const int lane = threadIdx.x & 31, warp = threadIdx.x >> 5;
    const int wrow = warp & 1, wcol = warp >> 1;

    float4 acc[4][8];
#pragma unroll
    for (int i = 0; i < 4; i++)
#pragma unroll
        for (int j = 0; j < 8; j++) acc[i][j] = make_float4(0.f, 0.f, 0.f, 0.f);

    gemm_core_w(afh + (size_t)z * (NEL/2) + ((size_t)(bm >> 7) << 16),
                afl + (size_t)z * (NEL/2) + ((size_t)(bm >> 7) << 16),
                bfh + (size_t)z * (NW/2)  + ((size_t)(bn >> 7) << 16),
                bfl + (size_t)z * (NW/2)  + ((size_t)(bn >> 7) << 16),
                smg, acc);

    const float* bias = z == 0 ? bq : (z == 1 ? bk : bv);
    const float scale = z == 0 ? 8.0f : 1.0f;
    const int g = lane >> 2, tig = lane & 3;
#pragma unroll
    for (int i = 0; i < 4; i++) {
#pragma unroll
        for (int j = 0; j < 8; j++) {
            int m0 = bm + wrow * 64 + i * 16 + g;
            int n0 = bn + wcol * 64 + j * 8 + tig * 2;
            float b0 = bias[n0], b1 = bias[n0 + 1];
            float x0 = (acc[i][j].x + b0) * scale, x1 = (acc[i][j].y + b1) * scale;
            float x2 = (acc[i][j].z + b0) * scale, x3 = (acc[i][j].w + b1) * scale;
            int b_ = m0 >> 10, hh_ = n0 >> 6, d = n0 & 63;
            if (z == 0) {
                int tt = (m0 >> 7) & 7, mr = m0 & 127;
                size_t blk = ((size_t)((b_ * 8 + tt) * 16 + hh_)) << 12;
                int addr = ((d >> 4) * 8 + (mr >> 4)) * 128
                         + ((mr & 7) * 4 + ((d >> 1) & 3)) * 4
                         + ((mr >> 3) & 1) + 2 * ((d >> 3) & 1);
                unsigned hw, lw;
                split_pair(x0, x1, hw, lw);
                qfh[blk + addr] = hw; qfl[blk + addr] = lw;
                split_pair(x2, x3, hw, lw);
                qfh[blk + addr + 1] = hw; qfl[blk + addr + 1] = lw;
            } else if (z == 1) {
                int stt = (m0 >> 6) & 15, sr = m0 & 63;
                size_t blk = ((size_t)((b_ * 16 + stt) * 16 + hh_)) << 11;
                int addr = ((d >> 4) * 8 + (sr >> 3)) * 64
                         + ((sr & 7) * 4 + ((d >> 1) & 3)) * 2 + ((d >> 3) & 1);
                unsigned hw, lw;
                split_pair(x0, x1, hw, lw);
                kfh[blk + addr] = hw; kfl[blk + addr] = lw;
                split_pair(x2, x3, hw, lw);
                kfh[blk + addr + 64] = hw; kfl[blk + addr + 64] = lw;
            } else {
                int stt = (m0 >> 6) & 15, sr = m0 & 63;
                size_t blk = ((size_t)((b_ * 16 + stt) * 16 + hh_)) << 12;
                int a00 = ((sr >> 3) * 8 + (d >> 3)) * 64
                        + ((d & 7) * 4 + (sr & 3)) * 2 + ((sr >> 2) & 1);
                vtf[blk + a00]           = f2tf32(x0);
                vtf[blk + a00 + 8]       = f2tf32(x1);
                vtf[blk + a00 + 512]     = f2tf32(x2);
                vtf[blk + a00 + 8 + 512] = f2tf32(x3);
            }
        }
    }
}

// ========== output projection GEMM, 128x256 block (fp32 row-major out) ==========
__global__ __launch_bounds__(256, 1)
void gemm_out(const unsigned* __restrict__ ctxfh, const unsigned* __restrict__ ctxfl,
              const unsigned* __restrict__ bfh, const unsigned* __restrict__ bfl,
              const float* __restrict__ bias, float* __restrict__ o0)
{
    extern __shared__ unsigned smg[];
    const int bm = blockIdx.y * 128, bn = blockIdx.x * 256;
    const int lane = threadIdx.x & 31, warp = threadIdx.x >> 5;
    const int wrow = warp & 1, wcol = warp >> 1;

    float4 acc[4][8];
#pragma unroll
    for (int i = 0; i < 4; i++)
#pragma unroll
        for (int j = 0; j < 8; j++) acc[i][j] = make_float4(0.f, 0.f, 0.f, 0.f);

    gemm_core_w(ctxfh + ((size_t)(bm >> 7) << 16),
                ctxfl + ((size_t)(bm >> 7) << 16),
                bfh + ((size_t)(bn >> 7) << 16),
                bfl + ((size_t)(bn >> 7) << 16),
                smg, acc);

    const int g = lane >> 2, tig = lane & 3;
#pragma unroll
    for (int i = 0; i < 4; i++) {
#pragma unroll
        for (int j = 0; j < 8; j++) {
            int m0 = bm + wrow * 64 + i * 16 + g;
            int n0 = bn + wcol * 64 + j * 8 + tig * 2;
            float b0 = bias[n0], b1 = bias[n0 + 1];
            size_t i0 = (size_t)m0 * CC + n0, i1 = (size_t)(m0 + 8) * CC + n0;
            *(float2*)(o0 + i0) = make_float2(acc[i][j].x + b0, acc[i][j].y + b1);
            *(float2*)(o0 + i1) = make_float2(acc[i][j].z + b0, acc[i][j].w + b1);
        }
    }
}

// ============== flash attention (round-14 config — best measured) ==============
#define ZP2 66
#define OFF_KFH 0
#define OFF_KFL 4096
#define OFF_VF  8192
#define OFF_RF  16384
#define OFF_PFS 28672
#define OFF_ZS  36864
#define FLASH6_WORDS (36864 + 128*ZP2)
#define FLASH6_SMEM (FLASH6_WORDS * 4)

__global__ __launch_bounds__(256)
void flash_mma6(const unsigned* __restrict__ qfh, const unsigned* __restrict__ qfl,
                const unsigned* __restrict__ qrg,
                const unsigned* __restrict__ kfh, const unsigned* __restrict__ kfl,
                const unsigned* __restrict__ vtf, const unsigned* __restrict__ rtf,
                unsigned* __restrict__ ctxfh, unsigned* __restrict__ ctxfl)
{
    extern __shared__ unsigned smu[];
    unsigned* kf_h = smu + OFF_KFH;
    unsigned* kf_l = smu + OFF_KFL;
    unsigned* vf   = smu + OFF_VF;
    unsigned* rf   = smu + OFF_RF;
    unsigned* pfs  = smu + OFF_PFS;
    float* Zs      = (float*)(smu + OFF_ZS);
    const unsigned sbase = (unsigned)__cvta_generic_to_shared(smu);

    const int tid = threadIdx.x;
    const int lane = tid & 31;
    const int w = tid >> 5;
    const int g = lane >> 2, tig = lane & 3;
    const int b = blockIdx.y >> 4, hq = blockIdx.y & 15;
    const int bx = blockIdx.x, t0 = bx * 128;
    unsigned* pf = pfs + w * 1024;
    const int m0 = w * 16 + g, m1 = m0 + 8;

#define KV_ISSUE(i_, buf_) { \
        size_t kb_ = (size_t)((b * 16 + (i_)) * 16 + hq); \
        const unsigned* khp = kfh + (kb_ << 11); \
        const unsigned* klp = kfl + (kb_ << 11); \
        const unsigned* vp  = vtf + (kb_ << 12); \
        _Pragma("unroll") \
        for (int x = 0; x < 2; x++) { \
            CP16(sbase + (OFF_KFH + (buf_) * 2048 + (tid + 256 * x) * 4) * 4, khp + (tid + 256 * x) * 4); \
            CP16(sbase + (OFF_KFL + (buf_) * 2048 + (tid + 256 * x) * 4) * 4, klp + (tid + 256 * x) * 4); \
        } \
        _Pragma("unroll") \
        for (int x = 0; x < 4; x++) \
            CP16(sbase + (OFF_VF + (buf_) * 4096 + (tid + 256 * x) * 4) * 4, vp + (tid + 256 * x) * 4); \
    }
    KV_ISSUE(0, 0); CP_COMMIT();

    uint4 qh[4], ql[4], qr[8];
    {
        size_t qblk = ((size_t)((b * 8 + bx) * 16 + hq));
        const uint4* qh4 = (const uint4*)(qfh + (qblk << 12));
        const uint4* ql4 = (const uint4*)(qfl + (qblk << 12));
        const uint4* qr4 = (const uint4*)(qrg + (qblk << 13));
#pragma unroll
        for (int kb = 0; kb < 4; kb++) {
            qh[kb] = qh4[(kb * 8 + w) * 32 + lane];
            ql[kb] = ql4[(kb * 8 + w) * 32 + lane];
        }
#pragma unroll
        for (int ks = 0; ks < 8; ks++)
            qr[ks] = qr4[(ks * 8 + w) * 32 + lane];
    }

    float m_i[2] = {-1e30f, -1e30f}, l_i[2] = {0.f, 0.f};
    float4 o[8];
#pragma unroll
    for (int j = 0; j < 8; j++) o[j] = make_float4(0.f, 0.f, 0.f, 0.f);

    for (int i = 0; i < 16; i++) {
        int T = i - 2 * bx + 14;
        const int buf = i & 1;
        __syncthreads();

        {
            if (i == 0) {
#pragma unroll
                for (int it = 0; it < 2; it++) {
                    const uint4* rs = (const uint4*)(rtf + (size_t)(T + it) * 4096);
                    uint4* rd = (uint4*)(rf + ((T + it) % 3) * 4096);
#pragma unroll
                    for (int x = 0; x < 4; x++) rd[tid + 256 * x] = rs[tid + 256 * x];
                }
            }
            const uint4* rs = (const uint4*)(rtf + (size_t)(T + 2) * 4096);
            uint4* rd = (uint4*)(rf + ((T + 2) % 3) * 4096);
#pragma unroll
            for (int x = 0; x < 4; x++) rd[tid + 256 * x] = rs[tid + 256 * x];
        }

        if (i < 15) KV_ISSUE(i + 1, buf ^ 1);
        CP_COMMIT();
        CP_WAIT1();
        __syncthreads();

        {
            const unsigned* rslot[3] = { rf + (T % 3) * 4096,
                                         rf + ((T + 1) % 3) * 4096,
                                         rf + ((T + 2) % 3) * 4096 };
            float4 zc[10];
#pragma unroll
            for (int j = 0; j < 10; j++) zc[j] = make_float4(0.f, 0.f, 0.f, 0.f);
#pragma unroll
            for (int ks = 0; ks < 8; ks++) {
#pragma unroll
                for (int j = 0; j < 10; j++) {
                    int nt = 14 - 2 * w + j;
                    uint2 bb = *(const uint2*)(rslot[nt >> 3] + (ks * 8 + (nt & 7)) * 64 + lane * 2);
                    mma_tf32(zc[j], qr[ks], bb);
                }
            }
#pragma unroll
            for (int j = 0; j < 10; j++) {
                int u = (14 - 2 * w + j) * 8 + 2 * tig;
                int s = u + m0 - 127;
                if ((unsigned)s < 64u)       Zs[m0 * ZP2 + s]     = zc[j].x;
                if ((unsigned)(s + 1) < 64u) Zs[m0 * ZP2 + s + 1] = zc[j].y;
                int s2 = s + 8;
                if ((unsigned)s2 < 64u)       Zs[m1 * ZP2 + s2]     = zc[j].z;
                if ((unsigned)(s2 + 1) < 64u) Zs[m1 * ZP2 + s2 + 1] = zc[j].w;
            }
        }
        __syncwarp();

        const unsigned* kh_ = kf_h + buf * 2048;
        const unsigned* kl_ = kf_l + buf * 2048;
        const unsigned* vf_ = vf + buf * 4096;
        float4 sc[8];
#pragma unroll
        for (int j = 0; j < 8; j++) sc[j] = make_float4(0.f, 0.f, 0.f, 0.f);
#pragma unroll
        for (int kb = 0; kb < 4; kb++) {
#pragma unroll
            for (int nt = 0; nt < 8; nt++) {
                uint2 bh = *(const uint2*)(kh_ + (kb * 8 + nt) * 64 + lane * 2);
                uint2 bl = *(const uint2*)(kl_ + (kb * 8 + nt) * 64 + lane * 2);
                mma_bf16(sc[nt], qh[kb], bl);
                mma_bf16(sc[nt], ql[kb], bh);
                mma_bf16(sc[nt], qh[kb], bh);
            }
        }

        float v0[16], v1[16];
#pragma unroll
        for (int nt = 0; nt < 8; nt++) {
            int s = nt * 8 + 2 * tig;
            v0[2*nt]   = sc[nt].x + Zs[m0 * ZP2 + s];
            v0[2*nt+1] = sc[nt].y + Zs[m0 * ZP2 + s + 1];
            v1[2*nt]   = sc[nt].z + Zs[m1 * ZP2 + s];
            v1[2*nt+1] = sc[nt].w + Zs[m1 * ZP2 + s + 1];
        }
        float lm0 = v0[0], lm1 = v1[0];
#pragma unroll
        for (int e = 1; e < 16; e++) { lm0 = fmaxf(lm0, v0[e]); lm1 = fmaxf(lm1, v1[e]); }
        lm0 = fmaxf(lm0, __shfl_xor_sync(~0u, lm0, 1));
        lm0 = fmaxf(lm0, __shfl_xor_sync(~0u, lm0, 2));
        lm1 = fmaxf(lm1, __shfl_xor_sync(~0u, lm1, 1));
        lm1 = fmaxf(lm1, __shfl_xor_sync(~0u, lm1, 2));
        float mn0 = fmaxf(m_i[0], lm0), mn1 = fmaxf(m_i[1], lm1);
        float al0 = __expf(m_i[0] - mn0), al1 = __expf(m_i[1] - mn1);
        m_i[0] = mn0; m_i[1] = mn1;
        float rs0 = 0.f, rs1 = 0.f;
#pragma unroll
        for (int nt = 0; nt < 8; nt++) {
            int s = nt * 8 + 2 * tig;
            float p00 = __expf(v0[2*nt]   - mn0);
            float p01 = __expf(v0[2*nt+1] - mn0);
            float p10 = __expf(v1[2*nt]   - mn1);
            float p11 = __expf(v1[2*nt+1] - mn1);
            rs0 += p00 + p01; rs1 += p10 + p11;
            int base = nt * 128 + (g * 4 + (s & 3)) * 4 + 2 * ((s >> 2) & 1);
            pf[base]     = f2tf32(p00);
            pf[base + 1] = f2tf32(p10);
            pf[base + 4] = f2tf32(p01);
            pf[base + 5] = f2tf32(p11);
        }
        rs0 += __shfl_xor_sync(~0u, rs0, 1); rs0 += __shfl_xor_sync(~0u, rs0, 2);
        rs1 += __shfl_xor_sync(~0u, rs1, 1); rs1 += __shfl_xor_sync(~0u, rs1, 2);
        l_i[0] = l_i[0] * al0 + rs0;
        l_i[1] = l_i[1] * al1 + rs1;
#pragma unroll
        for (int j = 0; j < 8; j++) {
            o[j].x *= al0; o[j].y *= al0; o[j].z *= al1; o[j].w *= al1;
        }
        __syncwarp();

#pragma unroll
        for (int ks = 0; ks < 8; ks++) {
            uint4 a = *(const uint4*)(pf + ks * 128 + lane * 4);
#pragma unroll
            for (int nt = 0; nt < 8; nt++) {
                uint2 bb = *(const uint2*)(vf_ + (ks * 8 + nt) * 64 + lane * 2);
                mma_tf32(o[nt], a, bb);
            }
        }
    }
#undef KV_ISSUE

    float inv0 = 1.f / l_i[0], inv1 = 1.f / l_i[1];
#pragma unroll
    for (int nt = 0; nt < 8; nt++) {
        int c = hq * HD + nt * 8 + 2 * tig;
        int mg0 = b * TT + t0 + m0, mg1 = b * TT + t0 + m1;
        unsigned hh, ll;
        split_pair(o[nt].x * inv0, o[nt].y * inv0, hh, ll);
        size_t a0 = afrag_addr(mg0, c);
        ctxfh[a0] = hh; ctxfl[a0] = ll;
        split_pair(o[nt].z * inv1, o[nt].w * inv1, hh, ll);
        size_t a1 = afrag_addr(mg1, c);
        ctxfh[a1] = hh; ctxfl[a1] = ll;
    }
}

// ------------------------------ launch ------------------------------
extern "C" void kernel_launch(void* const* d_in, const int* in_sizes, int n_in,
                              void* d_out, int out_size)
{
    const float* query   = (const float*)d_in[0];
    const float* key     = (const float*)d_in[1];
    const float* value   = (const float*)d_in[2];
    const float* Wq      = (const float*)d_in[3];
    const float* bq      = (const float*)d_in[4];
    const float* Wk      = (const float*)d_in[5];
    const float* bk      = (const float*)d_in[6];
    const float* Wv      = (const float*)d_in[7];
    const float* bv      = (const float*)d_in[8];
    const float* Wo      = (const float*)d_in[9];
    const float* bo      = (const float*)d_in[10];
    const float* rel_emb = (const float*)d_in[11];
    float* out = (float*)d_out;

    unsigned *afh, *afl, *bfh, *bfl, *qfh, *qfl, *kfh, *kfl, *vtf, *qrf, *rtf, *ctxfh, *ctxfl;
    cudaGetSymbolAddress((void**)&afh, g_afh);
    cudaGetSymbolAddress((void**)&afl, g_afl);
    cudaGetSymbolAddress((void**)&bfh, g_bfh);
    cudaGetSymbolAddress((void**)&bfl, g_bfl);
    cudaGetSymbolAddress((void**)&qfh, g_qfh);
    cudaGetSymbolAddress((void**)&qfl, g_qfl);
    cudaGetSymbolAddress((void**)&kfh, g_kfh);
    cudaGetSymbolAddress((void**)&kfl, g_kfl);
    cudaGetSymbolAddress((void**)&vtf, g_vtf);
    cudaGetSymbolAddress((void**)&qrf, g_qrf);
    cudaGetSymbolAddress((void**)&rtf, g_rtf);
    cudaGetSymbolAddress((void**)&ctxfh, g_ctxfh);
    cudaGetSymbolAddress((void**)&ctxfl, g_ctxfl);

    convAll<<<16896, 256>>>(query, key, value, Wq, Wk, Wv, Wo, rel_emb,
                            afh, afl, qrf, bfh, bfl, rtf);

    cudaFuncSetAttribute(gemm_qkv, cudaFuncAttributeMaxDynamicSharedMemorySize, GEMM_SMEM_W);
    cudaFuncSetAttribute(gemm_out, cudaFuncAttributeMaxDynamicSharedMemorySize, GEMM_SMEM_W);

    dim3 gqkv(CC / 256, (BB * TT) / 128, 3);    // (4, 32, 3) = 384 CTAs
    gemm_qkv<<<gqkv, 256, GEMM_SMEM_W>>>(afh, afl, bfh, bfl, bq, bk, bv,
                                         qfh, qfl, kfh, kfl, vtf);

    cudaFuncSetAttribute(flash_mma6, cudaFuncAttributeMaxDynamicSharedMemorySize, FLASH6_SMEM);
    flash_mma6<<<dim3(TT / 128, BB * HH), 256, FLASH6_SMEM>>>(
        qfh, qfl, qrf, kfh, kfl, vtf, rtf, ctxfh, ctxfl);

    dim3 gout(CC / 256, (BB * TT) / 128);       // (4, 32) = 128 CTAs — one wave
    gemm_out<<<gout, 256, GEMM_SMEM_W>>>(ctxfh, ctxfl, bfh + 3*(size_t)(NW/2),
                                         bfl + 3*(size_t)(NW/2), bo, out);
}

// round 17
// speedup vs baseline: 1.0126x; 1.0126x over previous
#include <cuda_runtime.h>
#include <cuda_bf16.h>
#include <stdint.h>
#include <math.h>

#define BB 4
#define TT 1024
#define CC 1024
#define HH 16
#define HD 64
#define NEL (BB*TT*CC)          // 4194304
#define NW  (CC*CC)             // 1048576

// ---------------- scratch (device globals: allocation-free) ----------------
__device__ unsigned g_afh[3][NEL/2], g_afl[3][NEL/2];    // q/k/v inputs, A-frag tiles hi/lo
__device__ unsigned g_bfh[4][NW/2],  g_bfl[4][NW/2];     // Wq/Wk/Wv/Wo, B-frag tiles hi/lo
__device__ unsigned g_qfh[NEL/2], g_qfl[NEL/2];          // proj q (x8) flash A-frags
__device__ unsigned g_kfh[NEL/2], g_kfl[NEL/2];          // proj k flash B-frags
__device__ unsigned g_vtf[NEL];                          // proj v tf32 flash B-frags
__device__ unsigned g_qrf[NEL];                          // raw q x8 tf32 flash A-frags
__device__ unsigned g_rtf[32*4096];                      // relpad tf32 B-frag tiles
__device__ unsigned g_ctxfh[NEL/2], g_ctxfl[NEL/2];      // attention out, A-frag tiles hi/lo

// ---------------- helpers ----------------
__device__ __forceinline__ unsigned f2tf32(float x) {
    unsigned u;
    asm("cvt.rna.tf32.f32 %0, %1;" : "=r"(u) : "f"(x));
    return u;
}
__device__ __forceinline__ void mma_tf32(float4& c, const uint4& a, const uint2& b) {
    asm volatile(
        "mma.sync.aligned.m16n8k8.row.col.f32.tf32.tf32.f32 "
        "{%0,%1,%2,%3}, {%4,%5,%6,%7}, {%8,%9}, {%0,%1,%2,%3};"
        : "+f"(c.x), "+f"(c.y), "+f"(c.z), "+f"(c.w)
        : "r"(a.x), "r"(a.y), "r"(a.z), "r"(a.w), "r"(b.x), "r"(b.y));
}
__device__ __forceinline__ void mma_bf16(float4& c, const uint4& a, const uint2& b) {
    asm volatile(
        "mma.sync.aligned.m16n8k16.row.col.f32.bf16.bf16.f32 "
        "{%0,%1,%2,%3}, {%4,%5,%6,%7}, {%8,%9}, {%0,%1,%2,%3};"
        : "+f"(c.x), "+f"(c.y), "+f"(c.z), "+f"(c.w)
        : "r"(a.x), "r"(a.y), "r"(a.z), "r"(a.w), "r"(b.x), "r"(b.y));
}
__device__ __forceinline__ void split_pair(float x, float y, unsigned& hi, unsigned& lo) {
    __nv_bfloat16 hx = __float2bfloat16(x), hy = __float2bfloat16(y);
    __nv_bfloat162 H; H.x = hx; H.y = hy;
    __nv_bfloat162 L;
    L.x = __float2bfloat16(x - __bfloat162float(hx));
    L.y = __float2bfloat16(y - __bfloat162float(hy));
    hi = *reinterpret_cast<unsigned*>(&H);
    lo = *reinterpret_cast<unsigned*>(&L);
}

#define CP16(d, p) asm volatile("cp.async.cg.shared.global [%0], [%1], 16;" :: "r"(d), "l"(p) : "memory")
#define CP_COMMIT() asm volatile("cp.async.commit_group;" ::: "memory")
#define CP_WAIT1()  asm volatile("cp.async.wait_group 1;" ::: "memory")

// A-frag word address for element pair (m, k even): within matrix [M,1024]
__device__ __forceinline__ size_t afrag_addr(int m, int k) {
    int mblk = m >> 7, mr = m & 127, kb = k >> 4, kk = k & 15;
    return (((size_t)mblk * 64 + kb) << 10) + (mr >> 4) * 128
         + ((mr & 7) * 4 + ((kk >> 1) & 3)) * 4 + ((mr >> 3) & 1) + 2 * (kk >> 3);
}
// B-frag word address for element pair (n, k even)
__device__ __forceinline__ size_t bfrag_addr(int n, int k) {
    int nblk = n >> 7, sr = n & 127, kb = k >> 4, kk = k & 15;
    return (((size_t)nblk * 64 + kb) << 10) + (sr >> 3) * 64
         + ((sr & 7) * 4 + ((kk >> 1) & 3)) * 2 + (kk >> 3);
}

// ---------------- fused one-time converts ----------------
__global__ void convAll(const float* __restrict__ q, const float* __restrict__ k,
                        const float* __restrict__ v,
                        const float* __restrict__ Wq, const float* __restrict__ Wk,
                        const float* __restrict__ Wv, const float* __restrict__ Wo,
                        const float* __restrict__ rel_emb,
                        unsigned* __restrict__ afh, unsigned* __restrict__ afl,
                        unsigned* __restrict__ qrf,
                        unsigned* __restrict__ bfh, unsigned* __restrict__ bfl,
                        unsigned* __restrict__ rtf)
{
    int blk = blockIdx.x;
    if (blk < 12288) {
        int arr = blk >> 12;
        int i = ((blk & 4095) << 8) + threadIdx.x;
        const float* src = arr == 0 ? q : (arr == 1 ? k : v);
        float4 v4 = ((const float4*)src)[i];
        unsigned h0, l0, h1, l1;
        split_pair(v4.x, v4.y, h0, l0);
        split_pair(v4.z, v4.w, h1, l1);
        int e = i * 4;
        int m = e >> 10, k0 = e & 1023;
        size_t base = (size_t)arr * (NEL/2) + afrag_addr(m, k0);
        afh[base] = h0; afh[base + 4] = h1;
        afl[base] = l0; afl[base + 4] = l1;
        if (arr == 0) {
            int hh_ = k0 >> 6, d = k0 & 63;
            int b_ = m >> 10, tt = (m >> 7) & 7, mr = m & 127;
            size_t blko = ((size_t)((b_ * 8 + tt) * 16 + hh_)) << 13;
            int qb = ((d >> 3) * 8 + (mr >> 4)) * 128 + (mr & 7) * 16
                   + ((mr >> 3) & 1) + 2 * ((d >> 2) & 1);
            qrf[blko + qb +  0] = f2tf32(8.f * v4.x);
            qrf[blko + qb +  4] = f2tf32(8.f * v4.y);
            qrf[blko + qb +  8] = f2tf32(8.f * v4.z);
            qrf[blko + qb + 12] = f2tf32(8.f * v4.w);
        }
    } else if (blk < 16384) {
        int wblk = blk - 12288;
        int arr = wblk >> 10;
        int i = ((wblk & 1023) << 8) + threadIdx.x;
        const float* src = arr == 0 ? Wq : (arr == 1 ? Wk : (arr == 2 ? Wv : Wo));
        float4 v4 = ((const float4*)src)[i];
        unsigned h0, l0, h1, l1;
        split_pair(v4.x, v4.y, h0, l0);
        split_pair(v4.z, v4.w, h1, l1);
        int e = i * 4;
        int n = e >> 10, k0 = e & 1023;
        size_t base = (size_t)arr * (NW/2) + bfrag_addr(n, k0);
        bfh[base] = h0; bfh[base + 2] = h1;
        bfl[base] = l0; bfl[base + 2] = l1;
    } else {
        int e = ((blk - 16384) << 8) + threadIdx.x;
        int tt = e >> 12, rem = e & 4095;
        int ul = rem >> 6, d = rem & 63;
        int u = tt * 64 + ul;
        int src = u - 24;
        src = src < 0 ? 0 : (src > 1998 ? 1998 : src);
        int addr = tt * 4096 + ((d >> 3) * 8 + (ul >> 3)) * 64
                 + ((ul & 7) * 4 + (d & 3)) * 2 + ((d >> 2) & 1);
        rtf[addr] = f2tf32(rel_emb[src * HD + d]);
    }
}

// ---------------- cp.async 3-stage GEMM core (128x128 block, K=1024) ----
__device__ __forceinline__ void gemm_core(const unsigned* __restrict__ Ahp,
                                          const unsigned* __restrict__ Alp,
                                          const unsigned* __restrict__ Bhp,
                                          const unsigned* __restrict__ Blp,
                                          unsigned* sm, float4 (&acc)[4][4])
{
    const int tid = threadIdx.x;
    const int lane = tid & 31;
    const int warp = tid >> 5;
    const int wrow = warp & 1, wcol = warp >> 1;
    const unsigned sbase = (unsigned)__cvta_generic_to_shared(sm);

#define GISSUE(kb_, s_) { \
        unsigned dd = sbase + (s_) * 16384 + (tid << 4); \
        int off = ((kb_) << 10) + (tid << 2); \
        CP16(dd,          Ahp + off); \
        CP16(dd + 4096,   Alp + off); \
        CP16(dd + 8192,   Bhp + off); \
        CP16(dd + 12288,  Blp + off); \
    }

    GISSUE(0, 0); CP_COMMIT();
    GISSUE(1, 1); CP_COMMIT();

    int st3 = 0;          // (kb % 3)
    int st3n = 2;         // ((kb+2) % 3)
    for (int kb = 0; kb < 64; kb++) {
        CP_WAIT1();
        __syncthreads();
        if (kb < 62) GISSUE(kb + 2, st3n);
        CP_COMMIT();

        const unsigned* st = sm + st3 * 4096;
        uint4 ah[4], al[4];
        uint2 bh[4], bl[4];
#pragma unroll
        for (int i = 0; i < 4; i++) {
            ah[i] = *(const uint4*)&st[(wrow * 4 + i) * 128 + lane * 4];
            al[i] = *(const uint4*)&st[1024 + (wrow * 4 + i) * 128 + lane * 4];
        }
#pragma unroll
        for (int j = 0; j < 4; j++) {
            bh[j] = *(const uint2*)&st[2048 + (wcol * 4 + j) * 64 + lane * 2];
            bl[j] = *(const uint2*)&st[3072 + (wcol * 4 + j) * 64 + lane * 2];
        }
#pragma unroll
        for (int i = 0; i < 4; i++)
#pragma unroll
            for (int j = 0; j < 4; j++) {
                mma_bf16(acc[i][j], ah[i], bl[j]);
                mma_bf16(acc[i][j], al[i], bh[j]);
                mma_bf16(acc[i][j], ah[i], bh[j]);
            }
        st3 = st3 == 2 ? 0 : st3 + 1;
        st3n = st3n == 2 ? 0 : st3n + 1;
    }
#undef GISSUE
}

#define GEMM_SMEM 49152

// ========== fused Q/K/V projection GEMM (blockIdx.z selects matrix + epilogue) ==========
__global__ __launch_bounds__(256, 2)
void gemm_qkv(const unsigned* __restrict__ afh, const unsigned* __restrict__ afl,
              const unsigned* __restrict__ bfh, const unsigned* __restrict__ bfl,
              const float* __restrict__ bq, const float* __restrict__ bk,
              const float* __restrict__ bv,
              unsigned* __restrict__ qfh, unsigned* __restrict__ qfl,
              unsigned* __restrict__ kfh, unsigned* __restrict__ kfl,
              unsigned* __restrict__ vtf)
{
    extern __shared__ unsigned smg[];
    const int z = blockIdx.z;
    const int bm = blockIdx.y * 128, bn = blockIdx.x * 128;
    const int lane = threadIdx.x & 31, warp = threadIdx.x >> 5;
    const int wrow = warp & 1, wcol = warp >> 1;

    float4 acc[4][4];
#pragma unroll
    for (int i = 0; i < 4; i++)
#pragma unroll
        for (int j = 0; j < 4; j++) acc[i][j] = make_float4(0.f, 0.f, 0.f, 0.f);

    gemm_core(afh + (size_t)z * (NEL/2) + ((size_t)(bm >> 7) << 16),
              afl + (size_t)z * (NEL/2) + ((size_t)(bm >> 7) << 16),
              bfh + (size_t)z * (NW/2)  + ((size_t)(bn >> 7) << 16),
              bfl + (size_t)z * (NW/2)  + ((size_t)(bn >> 7) << 16),
              smg, acc);

    const float* bias = z == 0 ? bq : (z == 1 ? bk : bv);
    const float scale = z == 0 ? 8.0f : 1.0f;
    const int g = lane >> 2, tig = lane & 3;
#pragma unroll
    for (int i = 0; i < 4; i++) {
#pragma unroll
        for (int j = 0; j < 4; j++) {
            int m0 = bm + wrow * 64 + i * 16 + g;
            int n0 = bn + wcol * 32 + j * 8 + tig * 2;
            float b0 = bias[n0], b1 = bias[n0 + 1];
            float x0 = (acc[i][j].x + b0) * scale, x1 = (acc[i][j].y + b1) * scale;
            float x2 = (acc[i][j].z + b0) * scale, x3 = (acc[i][j].w + b1) * scale;
            int b_ = m0 >> 10, hh_ = n0 >> 6, d = n0 & 63;
            if (z == 0) {
                int tt = (m0 >> 7) & 7, mr = m0 & 127;
                size_t blk = ((size_t)((b_ * 8 + tt) * 16 + hh_)) << 12;
                int addr = ((d >> 4) * 8 + (mr >> 4)) * 128
                         + ((mr & 7) * 4 + ((d >> 1) & 3)) * 4
                         + ((mr >> 3) & 1) + 2 * ((d >> 3) & 1);
                unsigned hw, lw;
                split_pair(x0, x1, hw, lw);
                qfh[blk + addr] = hw; qfl[blk + addr] = lw;
                split_pair(x2, x3, hw, lw);
                qfh[blk + addr + 1] = hw; qfl[blk + addr + 1] = lw;
            } else if (z == 1) {
                int stt = (m0 >> 6) & 15, sr = m0 & 63;
                size_t blk = ((size_t)((b_ * 16 + stt) * 16 + hh_)) << 11;
                int addr = ((d >> 4) * 8 + (sr >> 3)) * 64
                         + ((sr & 7) * 4 + ((d >> 1) & 3)) * 2 + ((d >> 3) & 1);
                unsigned hw, lw;
                split_pair(x0, x1, hw, lw);
                kfh[blk + addr] = hw; kfl[blk + addr] = lw;
                split_pair(x2, x3, hw, lw);
                kfh[blk + addr + 64] = hw; kfl[blk + addr + 64] = lw;
            } else {
                int stt = (m0 >> 6) & 15, sr = m0 & 63;
                size_t blk = ((size_t)((b_ * 16 + stt) * 16 + hh_)) << 12;
                int a00 = ((sr >> 3) * 8 + (d >> 3)) * 64
                        + ((d & 7) * 4 + (sr & 3)) * 2 + ((sr >> 2) & 1);
                vtf[blk + a00]           = f2tf32(x0);
                vtf[blk + a00 + 8]       = f2tf32(x1);
                vtf[blk + a00 + 512]     = f2tf32(x2);
                vtf[blk + a00 + 8 + 512] = f2tf32(x3);
            }
        }
    }
}

// ========== output projection GEMM (fp32 row-major out) ==========
__global__ __launch_bounds__(256, 2)
void gemm_out(const unsigned* __restrict__ ctxfh, const unsigned* __restrict__ ctxfl,
              const unsigned* __restrict__ bfh, const unsigned* __restrict__ bfl,
              const float* __restrict__ bias, float* __restrict__ o0)
{
    extern __shared__ unsigned smg[];
    const int bm = blockIdx.y * 128, bn = blockIdx.x * 128;
    const int lane = threadIdx.x & 31, warp = threadIdx.x >> 5;
    const int wrow = warp & 1, wcol = warp >> 1;

    float4 acc[4][4];
#pragma unroll
    for (int i = 0; i < 4; i++)
#pragma unroll
        for (int j = 0; j < 4; j++) acc[i][j] = make_float4(0.f, 0.f, 0.f, 0.f);

    gemm_core(ctxfh + ((size_t)(bm >> 7) << 16),
              ctxfl + ((size_t)(bm >> 7) << 16),
              bfh + ((size_t)(bn >> 7) << 16),
              bfl + ((size_t)(bn >> 7) << 16),
              smg, acc);

    const int g = lane >> 2, tig = lane & 3;
#pragma unroll
    for (int i = 0; i < 4; i++) {
#pragma unroll
        for (int j = 0; j < 4; j++) {
            int m0 = bm + wrow * 64 + i * 16 + g;
            int n0 = bn + wcol * 32 + j * 8 + tig * 2;
            float b0 = bias[n0], b1 = bias[n0 + 1];
            size_t i0 = (size_t)m0 * CC + n0, i1 = (size_t)(m0 + 8) * CC + n0;
            *(float2*)(o0 + i0) = make_float2(acc[i][j].x + b0, acc[i][j].y + b1);
            *(float2*)(o0 + i1) = make_float2(acc[i][j].z + b0, acc[i][j].w + b1);
        }
    }
}

// ============== flash attention: Q in registers, cp.async double-buffered K/V ==========
#define ZP2 66
#define OFF_KFH 0
#define OFF_KFL 4096
#define OFF_VF  8192
#define OFF_RF  16384
#define OFF_PFS 28672
#define OFF_ZS  36864
#define FLASH6_WORDS (36864 + 128*ZP2)
#define FLASH6_SMEM (FLASH6_WORDS * 4)     // 181248 B

__global__ __launch_bounds__(256)
void flash_mma6(const unsigned* __restrict__ qfh, const unsigned* __restrict__ qfl,
                const unsigned* __restrict__ qrg,
                const unsigned* __restrict__ kfh, const unsigned* __restrict__ kfl,
                const unsigned* __restrict__ vtf, const unsigned* __restrict__ rtf,
                unsigned* __restrict__ ctxfh, unsigned* __restrict__ ctxfl)
{
    extern __shared__ unsigned smu[];
    unsigned* kf_h = smu + OFF_KFH;   // [2][2048]
    unsigned* kf_l = smu + OFF_KFL;   // [2][2048]
    unsigned* vf   = smu + OFF_VF;    // [2][4096]
    unsigned* rf   = smu + OFF_RF;    // 3 ring slots x 4096
    unsigned* pfs  = smu + OFF_PFS;
    float* Zs      = (float*)(smu + OFF_ZS);
    const unsigned sbase = (unsigned)__cvta_generic_to_shared(smu);

    const int tid = threadIdx.x;
    const int lane = tid & 31;
    const int w = tid >> 5;
    const int g = lane >> 2, tig = lane & 3;
    const int b = blockIdx.y >> 4, hq = blockIdx.y & 15;
    const int bx = blockIdx.x, t0 = bx * 128;
    unsigned* pf = pfs + w * 1024;
    const int m0 = w * 16 + g, m1 = m0 + 8;

#define KV_ISSUE(i_, buf_) { \
        size_t kb_ = (size_t)((b * 16 + (i_)) * 16 + hq); \
        const unsigned* khp = kfh + (kb_ << 11); \
        const unsigned* klp = kfl + (kb_ << 11); \
        const unsigned* vp  = vtf + (kb_ << 12); \
        _Pragma("unroll") \
        for (int x = 0; x < 2; x++) { \
            CP16(sbase + (OFF_KFH + (buf_) * 2048 + (tid + 256 * x) * 4) * 4, khp + (tid + 256 * x) * 4); \
            CP16(sbase + (OFF_KFL + (buf_) * 2048 + (tid + 256 * x) * 4) * 4, klp + (tid + 256 * x) * 4); \
        } \
        _Pragma("unroll") \
        for (int x = 0; x < 4; x++) \
            CP16(sbase + (OFF_VF + (buf_) * 4096 + (tid + 256 * x) * 4) * 4, vp + (tid + 256 * x) * 4); \
    }
    KV_ISSUE(0, 0); CP_COMMIT();

    // ---- Q operands straight into registers (warp w only needs m-tile w) ----
    uint4 qh[4], ql[4], qr[8];
    {
        size_t qblk = ((size_t)((b * 8 + bx) * 16 + hq));
        const uint4* qh4 = (const uint4*)(qfh + (qblk << 12));
        const uint4* ql4 = (const uint4*)(qfl + (qblk << 12));
        const uint4* qr4 = (const uint4*)(qrg + (qblk << 13));
#pragma unroll
        for (int kb = 0; kb < 4; kb++) {
            qh[kb] = qh4[(kb * 8 + w) * 32 + lane];
            ql[kb] = ql4[(kb * 8 + w) * 32 + lane];
        }
#pragma unroll
        for (int ks = 0; ks < 8; ks++)
            qr[ks] = qr4[(ks * 8 + w) * 32 + lane];
    }

    float m_i[2] = {-1e30f, -1e30f}, l_i[2] = {0.f, 0.f};
    float4 o[8];
#pragma unroll
    for (int j = 0; j < 8; j++) o[j] = make_float4(0.f, 0.f, 0.f, 0.f);

    for (int i = 0; i < 16; i++) {
        int T = i - 2 * bx + 14;
        const int buf = i & 1;
        __syncthreads();   // prev-tile consumers done (rel slot + pf/vf reuse)

        // rel producer (synchronous; slot reuse safe after top sync)
        {
            if (i == 0) {
#pragma unroll
                for (int it = 0; it < 2; it++) {
                    const uint4* rs = (const uint4*)(rtf + (size_t)(T + it) * 4096);
                    uint4* rd = (uint4*)(rf + ((T + it) % 3) * 4096);
#pragma unroll
                    for (int x = 0; x < 4; x++) rd[tid + 256 * x] = rs[tid + 256 * x];
                }
            }
            const uint4* rs = (const uint4*)(rtf + (size_t)(T + 2) * 4096);
            uint4* rd = (uint4*)(rf + ((T + 2) % 3) * 4096);
#pragma unroll
            for (int x = 0; x < 4; x++) rd[tid + 256 * x] = rs[tid + 256 * x];
        }

        // issue K/V for tile i+1 into the other buffer (fire-and-forget)
        if (i < 15) KV_ISSUE(i + 1, buf ^ 1);
        CP_COMMIT();
        CP_WAIT1();        // tile i's K/V group complete
        __syncthreads();   // rel stores + cp.async data visible to all

        // ---- Z band mma (tf32) over 3-slot rel ring ----
        {
            const unsigned* rslot[3] = { rf + (T % 3) * 4096,
                                         rf + ((T + 1) % 3) * 4096,
                                         rf + ((T + 2) % 3) * 4096 };
            float4 zc[10];
#pragma unroll
            for (int j = 0; j < 10; j++) zc[j] = make_float4(0.f, 0.f, 0.f, 0.f);
#pragma unroll
            for (int ks = 0; ks < 8; ks++) {
#pragma unroll
                for (int j = 0; j < 10; j++) {
                    int nt = 14 - 2 * w + j;
                    uint2 bb = *(const uint2*)(rslot[nt >> 3] + (ks * 8 + (nt & 7)) * 64 + lane * 2);
                    mma_tf32(zc[j], qr[ks], bb);
                }
            }
#pragma unroll
            for (int j = 0; j < 10; j++) {
                int u = (14 - 2 * w + j) * 8 + 2 * tig;
                int s = u + m0 - 127;
                if ((unsigned)s < 64u)       Zs[m0 * ZP2 + s]     = zc[j].x;
                if ((unsigned)(s + 1) < 64u) Zs[m0 * ZP2 + s + 1] = zc[j].y;
                int s2 = s + 8;
                if ((unsigned)s2 < 64u)       Zs[m1 * ZP2 + s2]     = zc[j].z;
                if ((unsigned)(s2 + 1) < 64u) Zs[m1 * ZP2 + s2 + 1] = zc[j].w;
            }
        }
        __syncwarp();

        // ---- QK mma (3-term bf16), Q from registers ----
        const unsigned* kh_ = kf_h + buf * 2048;
        const unsigned* kl_ = kf_l + buf * 2048;
        const unsigned* vf_ = vf + buf * 4096;
        float4 sc[8];
#pragma unroll
        for (int j = 0; j < 8; j++) sc[j] = make_float4(0.f, 0.f, 0.f, 0.f);
#pragma unroll
        for (int kb = 0; kb < 4; kb++) {
#pragma unroll
            for (int nt = 0; nt < 8; nt++) {
                uint2 bh = *(const uint2*)(kh_ + (kb * 8 + nt) * 64 + lane * 2);
                uint2 bl = *(const uint2*)(kl_ + (kb * 8 + nt) * 64 + lane * 2);
                mma_bf16(sc[nt], qh[kb], bl);
                mma_bf16(sc[nt], ql[kb], bh);
                mma_bf16(sc[nt], qh[kb], bh);
            }
        }

        // ---- diag add + warp-local online softmax ----
        float v0[16], v1[16];
#pragma unroll
        for (int nt = 0; nt < 8; nt++) {
            int s = nt * 8 + 2 * tig;
            v0[2*nt]   = sc[nt].x + Zs[m0 * ZP2 + s];
            v0[2*nt+1] = sc[nt].y + Zs[m0 * ZP2 + s + 1];
            v1[2*nt]   = sc[nt].z + Zs[m1 * ZP2 + s];
            v1[2*nt+1] = sc[nt].w + Zs[m1 * ZP2 + s + 1];
        }
        float lm0 = v0[0], lm1 = v1[0];
#pragma unroll
        for (int e = 1; e < 16; e++) { lm0 = fmaxf(lm0, v0[e]); lm1 = fmaxf(lm1, v1[e]); }
        lm0 = fmaxf(lm0, __shfl_xor_sync(~0u, lm0, 1));
        lm0 = fmaxf(lm0, __shfl_xor_sync(~0u, lm0, 2));
        lm1 = fmaxf(lm1, __shfl_xor_sync(~0u, lm1, 1));
        lm1 = fmaxf(lm1, __shfl_xor_sync(~0u, lm1, 2));
        float mn0 = fmaxf(m_i[0], lm0), mn1 = fmaxf(m_i[1], lm1);
        float al0 = __expf(m_i[0] - mn0), al1 = __expf(m_i[1] - mn1);
        m_i[0] = mn0; m_i[1] = mn1;
        float rs0 = 0.f, rs1 = 0.f;
#pragma unroll
        for (int nt = 0; nt < 8; nt++) {
            int s = nt * 8 + 2 * tig;
            float p00 = __expf(v0[2*nt]   - mn0);
            float p01 = __expf(v0[2*nt+1] - mn0);
            float p10 = __expf(v1[2*nt]   - mn1);
            float p11 = __expf(v1[2*nt+1] - mn1);
            rs0 += p00 + p01; rs1 += p10 + p11;
            int base = nt * 128 + (g * 4 + (s & 3)) * 4 + 2 * ((s >> 2) & 1);
            pf[base]     = f2tf32(p00);
            pf[base + 1] = f2tf32(p10);
            pf[base + 4] = f2tf32(p01);
            pf[base + 5] = f2tf32(p11);
        }
        rs0 += __shfl_xor_sync(~0u, rs0, 1); rs0 += __shfl_xor_sync(~0u, rs0, 2);
        rs1 += __shfl_xor_sync(~0u, rs1, 1); rs1 += __shfl_xor_sync(~0u, rs1, 2);
        l_i[0] = l_i[0] * al0 + rs0;
        l_i[1] = l_i[1] * al1 + rs1;
#pragma unroll
        for (int j = 0; j < 8; j++) {
            o[j].x *= al0; o[j].y *= al0; o[j].z *= al1; o[j].w *= al1;
        }
        __syncwarp();

        // ---- PV mma (tf32): O += P @ V ----
#pragma unroll
        for (int ks = 0; ks < 8; ks++) {
            uint4 a = *(const uint4*)(pf + ks * 128 + lane * 4);
#pragma unroll
            for (int nt = 0; nt < 8; nt++) {
                uint2 bb = *(const uint2*)(vf_ + (ks * 8 + nt) * 64 + lane * 2);
                mma_tf32(o[nt], a, bb);
            }
        }
    }
#undef KV_ISSUE

    // epilogue: normalize, split, store in GEMM A-frag layout
    float inv0 = 1.f / l_i[0], inv1 = 1.f / l_i[1];
#pragma unroll
    for (int nt = 0; nt < 8; nt++) {
        int c = hq * HD + nt * 8 + 2 * tig;
        int mg0 = b * TT + t0 + m0, mg1 = b * TT + t0 + m1;
        unsigned hh, ll;
        split_pair(o[nt].x * inv0, o[nt].y * inv0, hh, ll);
        size_t a0 = afrag_addr(mg0, c);
        ctxfh[a0] = hh; ctxfl[a0] = ll;
        split_pair(o[nt].z * inv1, o[nt].w * inv1, hh, ll);
        size_t a1 = afrag_addr(mg1, c);
        ctxfh[a1] = hh; ctxfl[a1] = ll;
    }
}

// ------------------------------ launch ------------------------------
extern "C" void kernel_launch(void* const* d_in, const int* in_sizes, int n_in,
                              void* d_out, int out_size)
{
    const float* query   = (const float*)d_in[0];
    const float* key     = (const float*)d_in[1];
    const float* value   = (const float*)d_in[2];
    const float* Wq      = (const float*)d_in[3];
    const float* bq      = (const float*)d_in[4];
    const float* Wk      = (const float*)d_in[5];
    const float* bk      = (const float*)d_in[6];
    const float* Wv      = (const float*)d_in[7];
    const float* bv      = (const float*)d_in[8];
    const float* Wo      = (const float*)d_in[9];
    const float* bo      = (const float*)d_in[10];
    const float* rel_emb = (const float*)d_in[11];
    float* out = (float*)d_out;

    unsigned *afh, *afl, *bfh, *bfl, *qfh, *qfl, *kfh, *kfl, *vtf, *qrf, *rtf, *ctxfh, *ctxfl;
    cudaGetSymbolAddress((void**)&afh, g_afh);
    cudaGetSymbolAddress((void**)&afl, g_afl);
    cudaGetSymbolAddress((void**)&bfh, g_bfh);
    cudaGetSymbolAddress((void**)&bfl, g_bfl);
    cudaGetSymbolAddress((void**)&qfh, g_qfh);
    cudaGetSymbolAddress((void**)&qfl, g_qfl);
    cudaGetSymbolAddress((void**)&kfh, g_kfh);
    cudaGetSymbolAddress((void**)&kfl, g_kfl);
    cudaGetSymbolAddress((void**)&vtf, g_vtf);
    cudaGetSymbolAddress((void**)&qrf, g_qrf);
    cudaGetSymbolAddress((void**)&rtf, g_rtf);
    cudaGetSymbolAddress((void**)&ctxfh, g_ctxfh);
    cudaGetSymbolAddress((void**)&ctxfl, g_ctxfl);

    convAll<<<16896, 256>>>(query, key, value, Wq, Wk, Wv, Wo, rel_emb,
                            afh, afl, qrf, bfh, bfl, rtf);

    cudaFuncSetAttribute(gemm_qkv, cudaFuncAttributeMaxDynamicSharedMemorySize, GEMM_SMEM);
    cudaFuncSetAttribute(gemm_out, cudaFuncAttributeMaxDynamicSharedMemorySize, GEMM_SMEM);

    dim3 gqkv(CC / 128, (BB * TT) / 128, 3);
    gemm_qkv<<<gqkv, 256, GEMM_SMEM>>>(afh, afl, bfh, bfl, bq, bk, bv,
                                       qfh, qfl, kfh, kfl, vtf);

    cudaFuncSetAttribute(flash_mma6, cudaFuncAttributeMaxDynamicSharedMemorySize, FLASH6_SMEM);
    flash_mma6<<<dim3(TT / 128, BB * HH), 256, FLASH6_SMEM>>>(
        qfh, qfl, qrf, kfh, kfl, vtf, rtf, ctxfh, ctxfl);

    dim3 gout(CC / 128, (BB * TT) / 128);
    gemm_out<<<gout, 256, GEMM_SMEM>>>(ctxfh, ctxfl, bfh + 3*(size_t)(NW/2),
                                       bfl + 3*(size_t)(NW/2), bo, out);
}